// round 5
// baseline (speedup 1.0000x reference)
#include <cuda_runtime.h>
#include <cstdint>

#define Bv 4
#define Tv 512
#define Iv 128
#define Hv 128
#define Gv 512   // 4*H

// ---------------- device scratch (no allocations allowed) ----------------
__device__ __align__(16) float d_WihTs[Iv * Gv];        // [K=128][512]
__device__ __align__(16) float d_WhhTs[Hv * Gv];        // [K=128][512]
__device__ __align__(16) float d_WihTt[(Iv + Hv) * Gv]; // [K=256][512]
__device__ __align__(16) float d_WhhTt[Hv * Gv];        // [K=128][512]
__device__ __align__(16) float d_xg_s[Tv * Bv * Gv];    // [t][b][512]
__device__ __align__(16) float d_xg_t[Tv * Bv * Gv];    // [t][b][512]
__device__ __align__(16) float d_Hsh[Bv * Tv * Hv];     // [b][t][h]
__device__ __align__(16) float d_hpt[Bv * Tv * Hv];     // [b][t][n]
__device__ __align__(16) float d_ca [Bv * Tv * Hv];     // [b][s][n]  (xp + hp_s + bs)
__device__ __align__(16) float d_sc [Bv * Tv * Tv];     // [b][t][s]  scores -> beta
__device__ __align__(16) float d_R  [Bv * Tv * Hv];     // [b][t][h]

// ---------------- math helpers ----------------
__device__ __forceinline__ float fsig(float x) {
    // accurate enough (~1e-6): 1/(1+e^-x)
    return __fdividef(1.0f, 1.0f + __expf(-x));
}
__device__ __forceinline__ float ftanh_acc(float x) {
    x = fminf(15.0f, fmaxf(-15.0f, x));
    float e = __expf(2.0f * x);
    return __fdividef(e - 1.0f, e + 1.0f);
}
__device__ __forceinline__ float ftanh_fast(float x) {
    float y;
    asm("tanh.approx.f32 %0, %1;" : "=f"(y) : "f"(x));
    return y;
}

// ---------------- weight transpose: src [N,K] -> dst [K,N] ----------------
__global__ void k_transpose(const float* __restrict__ src, int which, int N, int K) {
    float* dst = (which == 0) ? d_WihTs : (which == 1) ? d_WhhTs
               : (which == 2) ? d_WihTt : d_WhhTt;
    __shared__ float tile[32][33];
    int n0 = blockIdx.y * 32, k0 = blockIdx.x * 32;
    int tx = threadIdx.x, ty = threadIdx.y;  // (32, 8)
    #pragma unroll
    for (int i = ty; i < 32; i += 8) {
        int n = n0 + i, k = k0 + tx;
        tile[i][tx] = (n < N && k < K) ? src[n * K + k] : 0.0f;
    }
    __syncthreads();
    #pragma unroll
    for (int i = ty; i < 32; i += 8) {
        int k = k0 + i, n = n0 + tx;
        if (k < K && n < N) dst[k * N + n] = tile[tx][i];
    }
}

// ---------------- input-gate projection: xg[t][b][n] = bias[n] + A1@W1 (+A2@W2) ----
// task=0: A1=x (K=128) with d_WihTs    -> d_xg_s
// task=1: A1=x, A2=d_R (K=256) with d_WihTt -> d_xg_t
__global__ __launch_bounds__(512) void k_proj_gates(
    const float* __restrict__ A1, const float* __restrict__ bias, int task) {
    int b = blockIdx.y;
    int t0 = blockIdx.x * 4;
    const float* WT = task ? d_WihTt : d_WihTs;
    float* out = task ? d_xg_t : d_xg_s;
    __shared__ float sa[4][256];
    int tid = threadIdx.x;
    {
        int tt = tid >> 7, k = tid & 127;  // 512 threads cover 4*128
        sa[tt][k] = A1[((b * Tv) + (t0 + tt)) * Iv + k];
        if (task) sa[tt][128 + k] = d_R[((b * Tv) + (t0 + tt)) * Hv + k];
    }
    __syncthreads();
    int n = tid;
    float bn = bias[n];
    float a0 = bn, a1 = bn, a2 = bn, a3 = bn;
    int K = task ? 256 : 128;
    #pragma unroll 4
    for (int k = 0; k < K; k++) {
        float w = WT[k * Gv + n];
        a0 = fmaf(w, sa[0][k], a0);
        a1 = fmaf(w, sa[1][k], a1);
        a2 = fmaf(w, sa[2][k], a2);
        a3 = fmaf(w, sa[3][k], a3);
    }
    out[((t0 + 0) * Bv + b) * Gv + n] = a0;
    out[((t0 + 1) * Bv + b) * Gv + n] = a1;
    out[((t0 + 2) * Bv + b) * Gv + n] = a2;
    out[((t0 + 3) * Bv + b) * Gv + n] = a3;
}

// ---------------- sequential LSTM: one block per batch ----------------
// threads: 512 = (j4 in [0,128)) x (kq in [0,4))
// task=0: xg=d_xg_s, W=d_WhhTs, out=d_Hsh ; task=1: xg=d_xg_t, W=d_WhhTt, out=out_ext
__global__ __launch_bounds__(512) void k_lstm(int task, float* __restrict__ out_ext) {
    int b = blockIdx.x;
    const float* __restrict__ xg   = task ? d_xg_t : d_xg_s;
    const float* __restrict__ WhhT = task ? d_WhhTt : d_WhhTs;
    float* __restrict__ Hout = task ? out_ext : d_Hsh;

    __shared__ __align__(16) float sh[Hv];
    __shared__ __align__(16) float sg[Gv];
    __shared__ __align__(16) float spart[3][Gv];

    int tid = threadIdx.x;
    int j4 = tid & 127;   // j group: outputs 4*j4 .. 4*j4+3
    int kq = tid >> 7;    // k quarter
    float c_reg = 0.0f;
    if (tid < Hv) sh[tid] = 0.0f;
    __syncthreads();

    const float4* __restrict__ W4 = reinterpret_cast<const float4*>(WhhT);

    for (int t = 0; t < Tv; t++) {
        float p0 = 0.f, p1 = 0.f, p2 = 0.f, p3 = 0.f;
        int kbase = kq * 32;
        #pragma unroll 8
        for (int kk = 0; kk < 32; kk++) {
            int k = kbase + kk;
            float hk = sh[k];
            float4 w = W4[k * 128 + j4];
            p0 = fmaf(w.x, hk, p0);
            p1 = fmaf(w.y, hk, p1);
            p2 = fmaf(w.z, hk, p2);
            p3 = fmaf(w.w, hk, p3);
        }
        if (kq != 0) {
            float4* sp = reinterpret_cast<float4*>(spart[kq - 1]);
            sp[j4] = make_float4(p0, p1, p2, p3);
        }
        __syncthreads();
        if (kq == 0) {
            const float4* xg4 = reinterpret_cast<const float4*>(xg + ((size_t)t * Bv + b) * Gv);
            float4 xv = xg4[j4];
            float4 q0 = reinterpret_cast<const float4*>(spart[0])[j4];
            float4 q1 = reinterpret_cast<const float4*>(spart[1])[j4];
            float4 q2 = reinterpret_cast<const float4*>(spart[2])[j4];
            sg[4 * j4 + 0] = p0 + q0.x + q1.x + q2.x + xv.x;
            sg[4 * j4 + 1] = p1 + q0.y + q1.y + q2.y + xv.y;
            sg[4 * j4 + 2] = p2 + q0.z + q1.z + q2.z + xv.z;
            sg[4 * j4 + 3] = p3 + q0.w + q1.w + q2.w + xv.w;
        }
        __syncthreads();
        if (tid < Hv) {
            int u = tid;
            float gi = sg[u];
            float gf = sg[Hv + u];
            float gg = sg[2 * Hv + u];
            float go = sg[3 * Hv + u];
            float iv = fsig(gi), fv = fsig(gf), ov = fsig(go);
            float gt = ftanh_acc(gg);
            c_reg = fv * c_reg + iv * gt;
            float hv = ov * ftanh_acc(c_reg);
            sh[u] = hv;
            Hout[((size_t)b * Tv + t) * Hv + u] = hv;
        }
        __syncthreads();
    }
}

// ---------------- attention projections ----------------
// hpt[b,t,n] = sum_k Hsh[b,t,k]*Wht[k,n]
// ca [b,s,n] = sum_k x[b,s,k]*Wx[k,n] + Hsh[b,s,k]*Whs[k,n] + bs[n]
__global__ __launch_bounds__(128) void k_att_proj(
    const float* __restrict__ x,
    const float* __restrict__ Wx, const float* __restrict__ Wht,
    const float* __restrict__ Whs, const float* __restrict__ bs) {
    int b = blockIdx.y;
    int t0 = blockIdx.x * 8;
    __shared__ float sx[8][Iv];
    __shared__ float shh[8][Hv];
    int tid = threadIdx.x;  // 128
    for (int i = tid; i < 8 * 128; i += 128) {
        int tt = i >> 7, k = i & 127;
        sx[tt][k]  = x[((b * Tv) + (t0 + tt)) * Iv + k];
        shh[tt][k] = d_Hsh[((b * Tv) + (t0 + tt)) * Hv + k];
    }
    __syncthreads();
    int n = tid;
    float at[8], ac[8];
    float bsn = bs[n];
    #pragma unroll
    for (int tt = 0; tt < 8; tt++) { at[tt] = 0.f; ac[tt] = bsn; }
    #pragma unroll 2
    for (int k = 0; k < 128; k++) {
        float wt = Wht[k * Hv + n];
        float ws = Whs[k * Hv + n];
        float wx = Wx [k * Hv + n];
        #pragma unroll
        for (int tt = 0; tt < 8; tt++) {
            at[tt] = fmaf(shh[tt][k], wt, at[tt]);
            ac[tt] = fmaf(sx[tt][k], wx, fmaf(shh[tt][k], ws, ac[tt]));
        }
    }
    #pragma unroll
    for (int tt = 0; tt < 8; tt++) {
        d_hpt[((b * Tv) + (t0 + tt)) * Hv + n] = at[tt];
        d_ca [((b * Tv) + (t0 + tt)) * Hv + n] = ac[tt];
    }
}

// ---------------- attention scores (the 134M-tanh kernel) ----------------
// scores[b,t,s] = sum_h u[h]*tanh(hpt[b,t,h] + ca[b,s,h]) + bu
__global__ __launch_bounds__(256) void k_scores(
    const float* __restrict__ u, const float* __restrict__ bu) {
    int b = blockIdx.z;
    int t0 = blockIdx.y * 32;
    int s0 = blockIdx.x * 32;
    __shared__ float sat[32][128];
    __shared__ float scs[32][129];
    __shared__ float su[128];
    int tid = threadIdx.y * 32 + threadIdx.x;  // 256
    for (int i = tid; i < 32 * 128; i += 256) {
        int r = i >> 7, h = i & 127;
        sat[r][h] = d_hpt[((b * Tv) + (t0 + r)) * Hv + h];
        scs[r][h] = d_ca [((b * Tv) + (s0 + r)) * Hv + h];
    }
    if (tid < 128) su[tid] = u[tid];
    __syncthreads();
    int si = threadIdx.x;       // 0..31
    int ti = threadIdx.y * 4;   // 0..28
    float a0 = 0.f, a1 = 0.f, a2 = 0.f, a3 = 0.f;
    #pragma unroll 4
    for (int h = 0; h < 128; h++) {
        float cv = scs[si][h];
        float uv = su[h];
        a0 = fmaf(uv, ftanh_fast(sat[ti + 0][h] + cv), a0);
        a1 = fmaf(uv, ftanh_fast(sat[ti + 1][h] + cv), a1);
        a2 = fmaf(uv, ftanh_fast(sat[ti + 2][h] + cv), a2);
        a3 = fmaf(uv, ftanh_fast(sat[ti + 3][h] + cv), a3);
    }
    float bub = bu[0];
    d_sc[((size_t)(b * Tv) + (t0 + ti + 0)) * Tv + s0 + si] = a0 + bub;
    d_sc[((size_t)(b * Tv) + (t0 + ti + 1)) * Tv + s0 + si] = a1 + bub;
    d_sc[((size_t)(b * Tv) + (t0 + ti + 2)) * Tv + s0 + si] = a2 + bub;
    d_sc[((size_t)(b * Tv) + (t0 + ti + 3)) * Tv + s0 + si] = a3 + bub;
}

// ---------------- softmax over s (in-place on d_sc) ----------------
__global__ __launch_bounds__(256) void k_softmax() {
    size_t row = blockIdx.x;  // b*T + t
    float* p = d_sc + row * Tv;
    int tid = threadIdx.x;
    float v0 = p[tid], v1 = p[tid + 256];
    __shared__ float red[256];
    red[tid] = fmaxf(v0, v1);
    __syncthreads();
    for (int off = 128; off > 0; off >>= 1) {
        if (tid < off) red[tid] = fmaxf(red[tid], red[tid + off]);
        __syncthreads();
    }
    float m = red[0];
    __syncthreads();
    float e0 = __expf(v0 - m), e1 = __expf(v1 - m);
    red[tid] = e0 + e1;
    __syncthreads();
    for (int off = 128; off > 0; off >>= 1) {
        if (tid < off) red[tid] = red[tid] + red[tid + off];
        __syncthreads();
    }
    float inv = __fdividef(1.0f, red[0]);
    p[tid] = e0 * inv;
    p[tid + 256] = e1 * inv;
}

// ---------------- R[b,t,h] = sum_s beta[b,t,s] * Hsh[b,s,h] ----------------
__global__ __launch_bounds__(128) void k_R() {
    int b = blockIdx.y;
    int t0 = blockIdx.x * 8;
    __shared__ float sb[8][Tv];
    int tid = threadIdx.x;  // 128
    for (int i = tid; i < 8 * Tv; i += 128) {
        int tt = i >> 9, s = i & 511;
        sb[tt][s] = d_sc[((size_t)(b * Tv) + (t0 + tt)) * Tv + s];
    }
    __syncthreads();
    float acc[8];
    #pragma unroll
    for (int tt = 0; tt < 8; tt++) acc[tt] = 0.f;
    int h = tid;
    #pragma unroll 4
    for (int s = 0; s < Tv; s++) {
        float hv = d_Hsh[((b * Tv) + s) * Hv + h];
        #pragma unroll
        for (int tt = 0; tt < 8; tt++) acc[tt] = fmaf(sb[tt][s], hv, acc[tt]);
    }
    #pragma unroll
    for (int tt = 0; tt < 8; tt++)
        d_R[((b * Tv) + (t0 + tt)) * Hv + h] = acc[tt];
}

// ---------------- launch ----------------
extern "C" void kernel_launch(void* const* d_in, const int* in_sizes, int n_in,
                              void* d_out, int out_size) {
    const float* x       = (const float*)d_in[0];
    const float* Wih_s   = (const float*)d_in[1];
    const float* Whh_s   = (const float*)d_in[2];
    const float* b_lstms = (const float*)d_in[3];
    const float* Wx      = (const float*)d_in[4];
    const float* Wht     = (const float*)d_in[5];
    const float* Whs     = (const float*)d_in[6];
    const float* bs      = (const float*)d_in[7];
    const float* u       = (const float*)d_in[8];
    const float* bu      = (const float*)d_in[9];
    const float* Wih_t   = (const float*)d_in[10];
    const float* Whh_t   = (const float*)d_in[11];
    const float* b_lstmt = (const float*)d_in[12];
    float* out = (float*)d_out;

    dim3 tb(32, 8);
    k_transpose<<<dim3(4, 16), tb>>>(Wih_s, 0, Gv, Iv);
    k_transpose<<<dim3(4, 16), tb>>>(Whh_s, 1, Gv, Hv);
    k_transpose<<<dim3(8, 16), tb>>>(Wih_t, 2, Gv, Iv + Hv);
    k_transpose<<<dim3(4, 16), tb>>>(Whh_t, 3, Gv, Hv);

    // shared LSTM
    k_proj_gates<<<dim3(Tv / 4, Bv), 512>>>(x, b_lstms, 0);
    k_lstm<<<Bv, 512>>>(0, out);

    // attention
    k_att_proj<<<dim3(Tv / 8, Bv), 128>>>(x, Wx, Wht, Whs, bs);
    k_scores<<<dim3(Tv / 32, Tv / 32, Bv), dim3(32, 8)>>>(u, bu);
    k_softmax<<<Bv * Tv, 256>>>();
    k_R<<<dim3(Tv / 8, Bv), 128>>>();

    // task LSTM
    k_proj_gates<<<dim3(Tv / 4, Bv), 512>>>(x, b_lstmt, 1);
    k_lstm<<<Bv, 512>>>(1, out);
}

// round 6
// speedup vs baseline: 2.1123x; 2.1123x over previous
#include <cuda_runtime.h>
#include <cuda_fp16.h>
#include <cstdint>

#define Bv 4
#define Tv 512
#define Iv 128
#define Hv 128
#define Gv 512   // 4*H

// ---------------- device scratch (no allocations allowed) ----------------
__device__ __align__(16) float d_WihTs[Iv * Gv];        // [K=128][512]
__device__ __align__(16) float d_WihTt[(Iv + Hv) * Gv]; // [K=256][512]
__device__ __align__(16) uint4 d_Wpks[64 * 128];        // fp16-packed Whh_s [k2][j4]
__device__ __align__(16) uint4 d_Wpkt[64 * 128];        // fp16-packed Whh_t [k2][j4]
__device__ __align__(16) float d_xg_s[Tv * Bv * Gv];    // [t][b][512]
__device__ __align__(16) float d_xg_t[Tv * Bv * Gv];    // [t][b][512]
__device__ __align__(16) float d_Hsh[Bv * Tv * Hv];     // [b][t][h]
__device__ __align__(16) float d_hpt[Bv * Tv * Hv];     // [b][t][n]
__device__ __align__(16) float d_ca [Bv * Tv * Hv];     // [b][s][n]  (xp + hp_s + bs)
__device__ __align__(16) float d_sc [Bv * Tv * Tv];     // [b][t][s]  scores -> beta
__device__ __align__(16) float d_R  [Bv * Tv * Hv];     // [b][t][h]

// ---------------- math helpers ----------------
__device__ __forceinline__ float fsig(float x) {
    return __fdividef(1.0f, 1.0f + __expf(-x));
}
__device__ __forceinline__ float ftanh_acc(float x) {
    x = fminf(15.0f, fmaxf(-15.0f, x));
    float e = __expf(2.0f * x);
    return __fdividef(e - 1.0f, e + 1.0f);
}
__device__ __forceinline__ float ftanh_fast(float x) {
    float y;
    asm("tanh.approx.f32 %0, %1;" : "=f"(y) : "f"(x));
    return y;
}
__device__ __forceinline__ uint32_t pack_h2(float a, float b) {
    __half2 h = __floats2half2_rn(a, b);
    return *reinterpret_cast<uint32_t*>(&h);
}
__device__ __forceinline__ float2 unpack_h2(uint32_t v) {
    __half2 h = *reinterpret_cast<__half2*>(&v);
    return __half22float2(h);
}

// ---------------- weight transpose: src [N,K] -> dst [K,N] (Wih only) -----
__global__ void k_transpose(const float* __restrict__ src, int which, int N, int K) {
    float* dst = (which == 0) ? d_WihTs : d_WihTt;
    __shared__ float tile[32][33];
    int n0 = blockIdx.y * 32, k0 = blockIdx.x * 32;
    int tx = threadIdx.x, ty = threadIdx.y;  // (32, 8)
    #pragma unroll
    for (int i = ty; i < 32; i += 8) {
        int n = n0 + i, k = k0 + tx;
        tile[i][tx] = (n < N && k < K) ? src[n * K + k] : 0.0f;
    }
    __syncthreads();
    #pragma unroll
    for (int i = ty; i < 32; i += 8) {
        int k = k0 + i, n = n0 + tx;
        if (k < K && n < N) dst[k * N + n] = tile[tx][i];
    }
}

// ---------------- pack Whh [512][128] f32 -> [k2][j4] uint4 of fp16 -------
// element (k2, j4): {h2(W[4j4][2k2],W[4j4+1][2k2]), h2(W[4j4+2][2k2],W[4j4+3][2k2]),
//                    h2(W[4j4][2k2+1],...),         h2(W[4j4+2][2k2+1],...)}
__global__ void k_pack(const float* __restrict__ W, int which) {
    uint4* dst = which ? d_Wpkt : d_Wpks;
    int idx = blockIdx.x * blockDim.x + threadIdx.x;  // 8192
    if (idx >= 64 * 128) return;
    int k2 = idx >> 7, j4 = idx & 127;
    int k0 = 2 * k2, n0 = 4 * j4;
    uint4 o;
    o.x = pack_h2(W[(n0 + 0) * 128 + k0],     W[(n0 + 1) * 128 + k0]);
    o.y = pack_h2(W[(n0 + 2) * 128 + k0],     W[(n0 + 3) * 128 + k0]);
    o.z = pack_h2(W[(n0 + 0) * 128 + k0 + 1], W[(n0 + 1) * 128 + k0 + 1]);
    o.w = pack_h2(W[(n0 + 2) * 128 + k0 + 1], W[(n0 + 3) * 128 + k0 + 1]);
    dst[idx] = o;
}

// ---------------- input-gate projection ----------------
__global__ __launch_bounds__(512) void k_proj_gates(
    const float* __restrict__ A1, const float* __restrict__ bias, int task) {
    int b = blockIdx.y;
    int t0 = blockIdx.x * 4;
    const float* WT = task ? d_WihTt : d_WihTs;
    float* out = task ? d_xg_t : d_xg_s;
    __shared__ float sa[4][256];
    int tid = threadIdx.x;
    {
        int tt = tid >> 7, k = tid & 127;
        sa[tt][k] = A1[((b * Tv) + (t0 + tt)) * Iv + k];
        if (task) sa[tt][128 + k] = d_R[((b * Tv) + (t0 + tt)) * Hv + k];
    }
    __syncthreads();
    int n = tid;
    float bn = bias[n];
    float a0 = bn, a1 = bn, a2 = bn, a3 = bn;
    int K = task ? 256 : 128;
    #pragma unroll 4
    for (int k = 0; k < K; k++) {
        float w = WT[k * Gv + n];
        a0 = fmaf(w, sa[0][k], a0);
        a1 = fmaf(w, sa[1][k], a1);
        a2 = fmaf(w, sa[2][k], a2);
        a3 = fmaf(w, sa[3][k], a3);
    }
    out[((t0 + 0) * Bv + b) * Gv + n] = a0;
    out[((t0 + 1) * Bv + b) * Gv + n] = a1;
    out[((t0 + 2) * Bv + b) * Gv + n] = a2;
    out[((t0 + 3) * Bv + b) * Gv + n] = a3;
}

// ---------------- sequential LSTM: one block per batch --------------------
// 512 threads = (j4 in [0,128)) x (kq in [0,4)); fp16 weights L1-resident.
__global__ __launch_bounds__(512) void k_lstm(int task, float* __restrict__ out_ext) {
    int b = blockIdx.x;
    const float* __restrict__ xg = task ? d_xg_t : d_xg_s;
    const uint4* __restrict__ Wp = task ? d_Wpkt : d_Wpks;
    float* __restrict__ Hout = task ? out_ext : d_Hsh;

    __shared__ __align__(16) float sh[Hv];
    __shared__ __align__(16) float sg[Gv];
    __shared__ __align__(16) float spart[3][Gv];

    int tid = threadIdx.x;
    int j4 = tid & 127;   // outputs 4*j4 .. 4*j4+3
    int kq = tid >> 7;    // k quarter (k2 in [16*kq, 16*kq+16))
    float c_reg = 0.0f;
    if (tid < Hv) sh[tid] = 0.0f;
    __syncthreads();

    for (int t = 0; t < Tv; t++) {
        // prefetch this step's xg (latency hidden under the MAC phase)
        float4 xv;
        if (kq == 0) {
            const float4* xg4 =
                reinterpret_cast<const float4*>(xg + ((size_t)t * Bv + b) * Gv);
            xv = __ldcs(xg4 + j4);
        }

        float p0 = 0.f, p1 = 0.f, p2 = 0.f, p3 = 0.f;
        int k2b = kq * 16;
        #pragma unroll
        for (int kk = 0; kk < 16; kk++) {
            int k2 = k2b + kk;
            uint4 w = Wp[k2 * 128 + j4];           // L1-hit after first step
            float2 h2 = *reinterpret_cast<const float2*>(sh + 2 * k2);
            float2 wa = unpack_h2(w.x);   // k even, n 0,1
            float2 wb = unpack_h2(w.y);   // k even, n 2,3
            float2 wc = unpack_h2(w.z);   // k odd,  n 0,1
            float2 wd = unpack_h2(w.w);   // k odd,  n 2,3
            p0 = fmaf(wa.x, h2.x, fmaf(wc.x, h2.y, p0));
            p1 = fmaf(wa.y, h2.x, fmaf(wc.y, h2.y, p1));
            p2 = fmaf(wb.x, h2.x, fmaf(wd.x, h2.y, p2));
            p3 = fmaf(wb.y, h2.x, fmaf(wd.y, h2.y, p3));
        }
        if (kq != 0) {
            float4* sp = reinterpret_cast<float4*>(spart[kq - 1]);
            sp[j4] = make_float4(p0, p1, p2, p3);
        }
        __syncthreads();
        if (kq == 0) {
            float4 q0 = reinterpret_cast<const float4*>(spart[0])[j4];
            float4 q1 = reinterpret_cast<const float4*>(spart[1])[j4];
            float4 q2 = reinterpret_cast<const float4*>(spart[2])[j4];
            sg[4 * j4 + 0] = p0 + q0.x + q1.x + q2.x + xv.x;
            sg[4 * j4 + 1] = p1 + q0.y + q1.y + q2.y + xv.y;
            sg[4 * j4 + 2] = p2 + q0.z + q1.z + q2.z + xv.z;
            sg[4 * j4 + 3] = p3 + q0.w + q1.w + q2.w + xv.w;
        }
        __syncthreads();
        if (tid < Hv) {
            int u = tid;
            float gi = sg[u];
            float gf = sg[Hv + u];
            float gg = sg[2 * Hv + u];
            float go = sg[3 * Hv + u];
            float iv = fsig(gi), fv = fsig(gf), ov = fsig(go);
            float gt = ftanh_acc(gg);
            c_reg = fv * c_reg + iv * gt;
            float hv = ov * ftanh_acc(c_reg);
            sh[u] = hv;
            Hout[((size_t)b * Tv + t) * Hv + u] = hv;
        }
        __syncthreads();
    }
}

// ---------------- attention projections ----------------
__global__ __launch_bounds__(128) void k_att_proj(
    const float* __restrict__ x,
    const float* __restrict__ Wx, const float* __restrict__ Wht,
    const float* __restrict__ Whs, const float* __restrict__ bs) {
    int b = blockIdx.y;
    int t0 = blockIdx.x * 8;
    __shared__ float sx[8][Iv];
    __shared__ float shh[8][Hv];
    int tid = threadIdx.x;  // 128
    for (int i = tid; i < 8 * 128; i += 128) {
        int tt = i >> 7, k = i & 127;
        sx[tt][k]  = x[((b * Tv) + (t0 + tt)) * Iv + k];
        shh[tt][k] = d_Hsh[((b * Tv) + (t0 + tt)) * Hv + k];
    }
    __syncthreads();
    int n = tid;
    float at[8], ac[8];
    float bsn = bs[n];
    #pragma unroll
    for (int tt = 0; tt < 8; tt++) { at[tt] = 0.f; ac[tt] = bsn; }
    #pragma unroll 2
    for (int k = 0; k < 128; k++) {
        float wt = Wht[k * Hv + n];
        float ws = Whs[k * Hv + n];
        float wx = Wx [k * Hv + n];
        #pragma unroll
        for (int tt = 0; tt < 8; tt++) {
            at[tt] = fmaf(shh[tt][k], wt, at[tt]);
            ac[tt] = fmaf(sx[tt][k], wx, fmaf(shh[tt][k], ws, ac[tt]));
        }
    }
    #pragma unroll
    for (int tt = 0; tt < 8; tt++) {
        d_hpt[((b * Tv) + (t0 + tt)) * Hv + n] = at[tt];
        d_ca [((b * Tv) + (t0 + tt)) * Hv + n] = ac[tt];
    }
}

// ---------------- attention scores ----------------
__global__ __launch_bounds__(256) void k_scores(
    const float* __restrict__ u, const float* __restrict__ bu) {
    int b = blockIdx.z;
    int t0 = blockIdx.y * 32;
    int s0 = blockIdx.x * 32;
    __shared__ float sat[32][128];
    __shared__ float scs[32][129];
    __shared__ float su[128];
    int tid = threadIdx.y * 32 + threadIdx.x;  // 256
    for (int i = tid; i < 32 * 128; i += 256) {
        int r = i >> 7, h = i & 127;
        sat[r][h] = d_hpt[((b * Tv) + (t0 + r)) * Hv + h];
        scs[r][h] = d_ca [((b * Tv) + (s0 + r)) * Hv + h];
    }
    if (tid < 128) su[tid] = u[tid];
    __syncthreads();
    int si = threadIdx.x;       // 0..31
    int ti = threadIdx.y * 4;   // 0..28
    float a0 = 0.f, a1 = 0.f, a2 = 0.f, a3 = 0.f;
    #pragma unroll 4
    for (int h = 0; h < 128; h++) {
        float cv = scs[si][h];
        float uv = su[h];
        a0 = fmaf(uv, ftanh_fast(sat[ti + 0][h] + cv), a0);
        a1 = fmaf(uv, ftanh_fast(sat[ti + 1][h] + cv), a1);
        a2 = fmaf(uv, ftanh_fast(sat[ti + 2][h] + cv), a2);
        a3 = fmaf(uv, ftanh_fast(sat[ti + 3][h] + cv), a3);
    }
    float bub = bu[0];
    d_sc[((size_t)(b * Tv) + (t0 + ti + 0)) * Tv + s0 + si] = a0 + bub;
    d_sc[((size_t)(b * Tv) + (t0 + ti + 1)) * Tv + s0 + si] = a1 + bub;
    d_sc[((size_t)(b * Tv) + (t0 + ti + 2)) * Tv + s0 + si] = a2 + bub;
    d_sc[((size_t)(b * Tv) + (t0 + ti + 3)) * Tv + s0 + si] = a3 + bub;
}

// ---------------- softmax over s (in-place on d_sc) ----------------
__global__ __launch_bounds__(256) void k_softmax() {
    size_t row = blockIdx.x;  // b*T + t
    float* p = d_sc + row * Tv;
    int tid = threadIdx.x;
    float v0 = p[tid], v1 = p[tid + 256];
    __shared__ float red[256];
    red[tid] = fmaxf(v0, v1);
    __syncthreads();
    for (int off = 128; off > 0; off >>= 1) {
        if (tid < off) red[tid] = fmaxf(red[tid], red[tid + off]);
        __syncthreads();
    }
    float m = red[0];
    __syncthreads();
    float e0 = __expf(v0 - m), e1 = __expf(v1 - m);
    red[tid] = e0 + e1;
    __syncthreads();
    for (int off = 128; off > 0; off >>= 1) {
        if (tid < off) red[tid] = red[tid] + red[tid + off];
        __syncthreads();
    }
    float inv = __fdividef(1.0f, red[0]);
    p[tid] = e0 * inv;
    p[tid + 256] = e1 * inv;
}

// ---------------- R[b,t,h] = sum_s beta[b,t,s] * Hsh[b,s,h] ----------------
__global__ __launch_bounds__(128) void k_R() {
    int b = blockIdx.y;
    int t0 = blockIdx.x * 8;
    __shared__ float sb[8][Tv];
    int tid = threadIdx.x;  // 128
    for (int i = tid; i < 8 * Tv; i += 128) {
        int tt = i >> 9, s = i & 511;
        sb[tt][s] = d_sc[((size_t)(b * Tv) + (t0 + tt)) * Tv + s];
    }
    __syncthreads();
    float acc[8];
    #pragma unroll
    for (int tt = 0; tt < 8; tt++) acc[tt] = 0.f;
    int h = tid;
    #pragma unroll 4
    for (int s = 0; s < Tv; s++) {
        float hv = d_Hsh[((b * Tv) + s) * Hv + h];
        #pragma unroll
        for (int tt = 0; tt < 8; tt++) acc[tt] = fmaf(sb[tt][s], hv, acc[tt]);
    }
    #pragma unroll
    for (int tt = 0; tt < 8; tt++)
        d_R[((b * Tv) + (t0 + tt)) * Hv + h] = acc[tt];
}

// ---------------- launch ----------------
extern "C" void kernel_launch(void* const* d_in, const int* in_sizes, int n_in,
                              void* d_out, int out_size) {
    const float* x       = (const float*)d_in[0];
    const float* Wih_s   = (const float*)d_in[1];
    const float* Whh_s   = (const float*)d_in[2];
    const float* b_lstms = (const float*)d_in[3];
    const float* Wx      = (const float*)d_in[4];
    const float* Wht     = (const float*)d_in[5];
    const float* Whs     = (const float*)d_in[6];
    const float* bs      = (const float*)d_in[7];
    const float* u       = (const float*)d_in[8];
    const float* bu      = (const float*)d_in[9];
    const float* Wih_t   = (const float*)d_in[10];
    const float* Whh_t   = (const float*)d_in[11];
    const float* b_lstmt = (const float*)d_in[12];
    float* out = (float*)d_out;

    dim3 tb(32, 8);
    k_transpose<<<dim3(4, 16), tb>>>(Wih_s, 0, Gv, Iv);
    k_transpose<<<dim3(8, 16), tb>>>(Wih_t, 1, Gv, Iv + Hv);
    k_pack<<<32, 256>>>(Whh_s, 0);
    k_pack<<<32, 256>>>(Whh_t, 1);

    // shared LSTM
    k_proj_gates<<<dim3(Tv / 4, Bv), 512>>>(x, b_lstms, 0);
    k_lstm<<<Bv, 512>>>(0, out);

    // attention
    k_att_proj<<<dim3(Tv / 8, Bv), 128>>>(x, Wx, Wht, Whs, bs);
    k_scores<<<dim3(Tv / 32, Tv / 32, Bv), dim3(32, 8)>>>(u, bu);
    k_softmax<<<Bv * Tv, 256>>>();
    k_R<<<dim3(Tv / 8, Bv), 128>>>();

    // task LSTM
    k_proj_gates<<<dim3(Tv / 4, Bv), 512>>>(x, b_lstmt, 1);
    k_lstm<<<Bv, 512>>>(1, out);
}

// round 7
// speedup vs baseline: 3.5480x; 1.6797x over previous
#include <cuda_runtime.h>
#include <cuda_fp16.h>
#include <cstdint>

#define Bv 4
#define Tv 512
#define Iv 128
#define Hv 128
#define Gv 512   // 4*H

// ---------------- device scratch (no allocations allowed) ----------------
__device__ __align__(16) float d_WihTs[Iv * Gv];        // [K=128][512]
__device__ __align__(16) float d_WihTt[(Iv + Hv) * Gv]; // [K=256][512]
__device__ __align__(16) uint4 d_Wfs[16 * 16 * 32];     // mma A-frags, shared LSTM
__device__ __align__(16) uint4 d_Wft[16 * 16 * 32];     // mma A-frags, task LSTM
__device__ __align__(16) float d_xg_s[Tv * Bv * Gv];    // [t][b][512]
__device__ __align__(16) float d_xg_t[Tv * Bv * Gv];    // [t][b][512]
__device__ __align__(16) float d_Hsh[Bv * Tv * Hv];     // [b][t][h]
__device__ __align__(16) float d_hpt[Bv * Tv * Hv];     // [b][t][n]
__device__ __align__(16) float d_ca [Bv * Tv * Hv];     // [b][s][n]
__device__ __align__(16) float d_sc [Bv * Tv * Tv];     // [b][t][s]
__device__ __align__(16) float d_R  [Bv * Tv * Hv];     // [b][t][h]

// ---------------- math helpers ----------------
__device__ __forceinline__ float fsig(float x) {
    return __fdividef(1.0f, 1.0f + __expf(-x));
}
__device__ __forceinline__ float ftanh_acc(float x) {
    x = fminf(15.0f, fmaxf(-15.0f, x));
    float e = __expf(2.0f * x);
    return __fdividef(e - 1.0f, e + 1.0f);
}
__device__ __forceinline__ float ftanh_fast(float x) {
    float y;
    asm("tanh.approx.f32 %0, %1;" : "=f"(y) : "f"(x));
    return y;
}
__device__ __forceinline__ uint32_t pack_h2(float a, float b) {
    __half2 h = __floats2half2_rn(a, b);
    return *reinterpret_cast<uint32_t*>(&h);
}
__device__ __forceinline__ void mma16816(float& d0, float& d1, float& d2, float& d3,
                                         uint4 a, uint32_t b0, uint32_t b1) {
    asm volatile(
        "mma.sync.aligned.m16n8k16.row.col.f32.f16.f16.f32 "
        "{%0,%1,%2,%3}, {%4,%5,%6,%7}, {%8,%9}, {%0,%1,%2,%3};"
        : "+f"(d0), "+f"(d1), "+f"(d2), "+f"(d3)
        : "r"(a.x), "r"(a.y), "r"(a.z), "r"(a.w), "r"(b0), "r"(b1));
}

// ---------------- weight transpose: src [N,K] -> dst [K,N] (Wih only) -----
__global__ void k_transpose(const float* __restrict__ src, int which, int N, int K) {
    float* dst = (which == 0) ? d_WihTs : d_WihTt;
    __shared__ float tile[32][33];
    int n0 = blockIdx.y * 32, k0 = blockIdx.x * 32;
    int tx = threadIdx.x, ty = threadIdx.y;  // (32, 8)
    #pragma unroll
    for (int i = ty; i < 32; i += 8) {
        int n = n0 + i, k = k0 + tx;
        tile[i][tx] = (n < N && k < K) ? src[n * K + k] : 0.0f;
    }
    __syncthreads();
    #pragma unroll
    for (int i = ty; i < 32; i += 8) {
        int k = k0 + i, n = n0 + tx;
        if (k < K && n < N) dst[k * N + n] = tile[tx][i];
    }
}

// ---------------- pack Whh [512][128] f32 into m16n8k16 A-fragments -------
// Entry e = ((warp*16)+i)*32 + lane; i -> (msub = i>>3, kt = i&7).
// A[m][k] = Whh[m*128+k]; fragment regs per PTX m16n8k16 layout.
__global__ void k_packw(const float* __restrict__ W, int which) {
    uint4* dst = which ? d_Wft : d_Wfs;
    int e = blockIdx.x * blockDim.x + threadIdx.x;  // 8192
    if (e >= 16 * 16 * 32) return;
    int w = e >> 9, i = (e >> 5) & 15, lane = e & 31;
    int m0 = (w * 2 + (i >> 3)) * 16;
    int k0 = (i & 7) * 16;
    int g = lane >> 2, tg = lane & 3;
    const float* Wm0 = W + (m0 + g) * 128;
    const float* Wm8 = W + (m0 + g + 8) * 128;
    uint4 o;
    o.x = pack_h2(Wm0[k0 + 2 * tg],     Wm0[k0 + 2 * tg + 1]);
    o.y = pack_h2(Wm8[k0 + 2 * tg],     Wm8[k0 + 2 * tg + 1]);
    o.z = pack_h2(Wm0[k0 + 2 * tg + 8], Wm0[k0 + 2 * tg + 9]);
    o.w = pack_h2(Wm8[k0 + 2 * tg + 8], Wm8[k0 + 2 * tg + 9]);
    dst[e] = o;
}

// ---------------- input-gate projection ----------------
__global__ __launch_bounds__(512) void k_proj_gates(
    const float* __restrict__ A1, const float* __restrict__ bias, int task) {
    int b = blockIdx.y;
    int t0 = blockIdx.x * 4;
    const float* WT = task ? d_WihTt : d_WihTs;
    float* out = task ? d_xg_t : d_xg_s;
    __shared__ float sa[4][256];
    int tid = threadIdx.x;
    {
        int tt = tid >> 7, k = tid & 127;
        sa[tt][k] = A1[((b * Tv) + (t0 + tt)) * Iv + k];
        if (task) sa[tt][128 + k] = d_R[((b * Tv) + (t0 + tt)) * Hv + k];
    }
    __syncthreads();
    int n = tid;
    float bn = bias[n];
    float a0 = bn, a1 = bn, a2 = bn, a3 = bn;
    int K = task ? 256 : 128;
    #pragma unroll 4
    for (int k = 0; k < K; k++) {
        float w = WT[k * Gv + n];
        a0 = fmaf(w, sa[0][k], a0);
        a1 = fmaf(w, sa[1][k], a1);
        a2 = fmaf(w, sa[2][k], a2);
        a3 = fmaf(w, sa[3][k], a3);
    }
    out[((t0 + 0) * Bv + b) * Gv + n] = a0;
    out[((t0 + 1) * Bv + b) * Gv + n] = a1;
    out[((t0 + 2) * Bv + b) * Gv + n] = a2;
    out[((t0 + 3) * Bv + b) * Gv + n] = a3;
}

// ---------------- sequential LSTM: ONE CTA for all 4 batches (HMMA) -------
// 512 threads = 16 warps; warp w owns m-tiles {2w, 2w+1} of G[512, n<=8].
// A (weights) register-resident fragments; B = h fp16 in smem; D -> gate smem.
#define HB_STRIDE 136   // halves per hb row (conflict-free)
#define SG_STRIDE 6     // floats per sgb row (8B-aligned float2 stores)
__global__ __launch_bounds__(512, 1) void k_lstm(int task, float* __restrict__ out_ext) {
    const float* __restrict__ xg = task ? d_xg_t : d_xg_s;
    const uint4* __restrict__ Wf = task ? d_Wft : d_Wfs;
    float* __restrict__ Hout = task ? out_ext : d_Hsh;

    __shared__ __align__(16) __half hb[8 * HB_STRIDE];     // B: [n][k] fp16
    __shared__ __align__(16) float sgb[512 * SG_STRIDE];   // G: [m][n] fp32

    int tid = threadIdx.x;
    int warp = tid >> 5, lane = tid & 31;
    int g = lane >> 2, tg = lane & 3;
    int bc = tid >> 7, uc = tid & 127;   // cell-update assignment (batch, unit)

    // load static A fragments (64 regs)
    uint4 af[16];
    #pragma unroll
    for (int i = 0; i < 16; i++) af[i] = Wf[(warp * 16 + i) * 32 + lane];

    // init h = 0 (including padding rows n=4..7)
    for (int j = tid; j < 8 * HB_STRIDE; j += 512) hb[j] = __float2half(0.0f);
    float c_reg = 0.0f;
    __syncthreads();

    for (int t = 0; t < Tv; t++) {
        // prefetch xg for this thread's cell (hidden under mma phase)
        const float* xr = xg + ((size_t)t * Bv + bc) * Gv + uc;
        float xgi = xr[0], xgf = xr[128], xgg = xr[256], xgo = xr[384];

        // load B fragments from hb
        uint32_t bf0[8], bf1[8];
        #pragma unroll
        for (int kt = 0; kt < 8; kt++) {
            int base = g * HB_STRIDE + kt * 16 + tg * 2;
            bf0[kt] = *reinterpret_cast<const uint32_t*>(&hb[base]);
            bf1[kt] = *reinterpret_cast<const uint32_t*>(&hb[base + 8]);
        }

        // 16 mma: 2 m-tiles x 8 k-tiles, interleaved accumulator chains
        float d0[4] = {0.f, 0.f, 0.f, 0.f};
        float d1[4] = {0.f, 0.f, 0.f, 0.f};
        #pragma unroll
        for (int kt = 0; kt < 8; kt++) {
            mma16816(d0[0], d0[1], d0[2], d0[3], af[kt],     bf0[kt], bf1[kt]);
            mma16816(d1[0], d1[1], d1[2], d1[3], af[8 + kt], bf0[kt], bf1[kt]);
        }

        // store D (only n<4 columns, i.e. tg<2)
        if (tg < 2) {
            int m0 = warp * 32;
            *reinterpret_cast<float2*>(&sgb[(m0 + g)      * SG_STRIDE + tg * 2]) = make_float2(d0[0], d0[1]);
            *reinterpret_cast<float2*>(&sgb[(m0 + g + 8)  * SG_STRIDE + tg * 2]) = make_float2(d0[2], d0[3]);
            *reinterpret_cast<float2*>(&sgb[(m0 + g + 16) * SG_STRIDE + tg * 2]) = make_float2(d1[0], d1[1]);
            *reinterpret_cast<float2*>(&sgb[(m0 + g + 24) * SG_STRIDE + tg * 2]) = make_float2(d1[2], d1[3]);
        }
        __syncthreads();

        // cell update: one (batch, unit) per thread
        {
            float gi = sgb[(uc)       * SG_STRIDE + bc] + xgi;
            float gf = sgb[(128 + uc) * SG_STRIDE + bc] + xgf;
            float gg = sgb[(256 + uc) * SG_STRIDE + bc] + xgg;
            float go = sgb[(384 + uc) * SG_STRIDE + bc] + xgo;
            float iv = fsig(gi), fv = fsig(gf), ov = fsig(go);
            float gt = ftanh_acc(gg);
            c_reg = fv * c_reg + iv * gt;
            float hv = ov * ftanh_acc(c_reg);
            hb[bc * HB_STRIDE + uc] = __float2half(hv);
            Hout[((size_t)bc * Tv + t) * Hv + uc] = hv;
        }
        __syncthreads();
    }
}

// ---------------- attention projections ----------------
__global__ __launch_bounds__(128) void k_att_proj(
    const float* __restrict__ x,
    const float* __restrict__ Wx, const float* __restrict__ Wht,
    const float* __restrict__ Whs, const float* __restrict__ bs) {
    int b = blockIdx.y;
    int t0 = blockIdx.x * 8;
    __shared__ float sx[8][Iv];
    __shared__ float shh[8][Hv];
    int tid = threadIdx.x;  // 128
    for (int i = tid; i < 8 * 128; i += 128) {
        int tt = i >> 7, k = i & 127;
        sx[tt][k]  = x[((b * Tv) + (t0 + tt)) * Iv + k];
        shh[tt][k] = d_Hsh[((b * Tv) + (t0 + tt)) * Hv + k];
    }
    __syncthreads();
    int n = tid;
    float at[8], ac[8];
    float bsn = bs[n];
    #pragma unroll
    for (int tt = 0; tt < 8; tt++) { at[tt] = 0.f; ac[tt] = bsn; }
    #pragma unroll 2
    for (int k = 0; k < 128; k++) {
        float wt = Wht[k * Hv + n];
        float ws = Whs[k * Hv + n];
        float wx = Wx [k * Hv + n];
        #pragma unroll
        for (int tt = 0; tt < 8; tt++) {
            at[tt] = fmaf(shh[tt][k], wt, at[tt]);
            ac[tt] = fmaf(sx[tt][k], wx, fmaf(shh[tt][k], ws, ac[tt]));
        }
    }
    #pragma unroll
    for (int tt = 0; tt < 8; tt++) {
        d_hpt[((b * Tv) + (t0 + tt)) * Hv + n] = at[tt];
        d_ca [((b * Tv) + (t0 + tt)) * Hv + n] = ac[tt];
    }
}

// ---------------- attention scores ----------------
__global__ __launch_bounds__(256) void k_scores(
    const float* __restrict__ u, const float* __restrict__ bu) {
    int b = blockIdx.z;
    int t0 = blockIdx.y * 32;
    int s0 = blockIdx.x * 32;
    __shared__ float sat[32][128];
    __shared__ float scs[32][129];
    __shared__ float su[128];
    int tid = threadIdx.y * 32 + threadIdx.x;  // 256
    for (int i = tid; i < 32 * 128; i += 256) {
        int r = i >> 7, h = i & 127;
        sat[r][h] = d_hpt[((b * Tv) + (t0 + r)) * Hv + h];
        scs[r][h] = d_ca [((b * Tv) + (s0 + r)) * Hv + h];
    }
    if (tid < 128) su[tid] = u[tid];
    __syncthreads();
    int si = threadIdx.x;       // 0..31
    int ti = threadIdx.y * 4;   // 0..28
    float a0 = 0.f, a1 = 0.f, a2 = 0.f, a3 = 0.f;
    #pragma unroll 4
    for (int h = 0; h < 128; h++) {
        float cv = scs[si][h];
        float uv = su[h];
        a0 = fmaf(uv, ftanh_fast(sat[ti + 0][h] + cv), a0);
        a1 = fmaf(uv, ftanh_fast(sat[ti + 1][h] + cv), a1);
        a2 = fmaf(uv, ftanh_fast(sat[ti + 2][h] + cv), a2);
        a3 = fmaf(uv, ftanh_fast(sat[ti + 3][h] + cv), a3);
    }
    float bub = bu[0];
    d_sc[((size_t)(b * Tv) + (t0 + ti + 0)) * Tv + s0 + si] = a0 + bub;
    d_sc[((size_t)(b * Tv) + (t0 + ti + 1)) * Tv + s0 + si] = a1 + bub;
    d_sc[((size_t)(b * Tv) + (t0 + ti + 2)) * Tv + s0 + si] = a2 + bub;
    d_sc[((size_t)(b * Tv) + (t0 + ti + 3)) * Tv + s0 + si] = a3 + bub;
}

// ---------------- softmax over s (in-place on d_sc) ----------------
__global__ __launch_bounds__(256) void k_softmax() {
    size_t row = blockIdx.x;  // b*T + t
    float* p = d_sc + row * Tv;
    int tid = threadIdx.x;
    float v0 = p[tid], v1 = p[tid + 256];
    __shared__ float red[256];
    red[tid] = fmaxf(v0, v1);
    __syncthreads();
    for (int off = 128; off > 0; off >>= 1) {
        if (tid < off) red[tid] = fmaxf(red[tid], red[tid + off]);
        __syncthreads();
    }
    float m = red[0];
    __syncthreads();
    float e0 = __expf(v0 - m), e1 = __expf(v1 - m);
    red[tid] = e0 + e1;
    __syncthreads();
    for (int off = 128; off > 0; off >>= 1) {
        if (tid < off) red[tid] = red[tid] + red[tid + off];
        __syncthreads();
    }
    float inv = __fdividef(1.0f, red[0]);
    p[tid] = e0 * inv;
    p[tid + 256] = e1 * inv;
}

// ---------------- R[b,t,h] = sum_s beta[b,t,s] * Hsh[b,s,h] ----------------
__global__ __launch_bounds__(128) void k_R() {
    int b = blockIdx.y;
    int t0 = blockIdx.x * 8;
    __shared__ float sb[8][Tv];
    int tid = threadIdx.x;  // 128
    for (int i = tid; i < 8 * Tv; i += 128) {
        int tt = i >> 9, s = i & 511;
        sb[tt][s] = d_sc[((size_t)(b * Tv) + (t0 + tt)) * Tv + s];
    }
    __syncthreads();
    float acc[8];
    #pragma unroll
    for (int tt = 0; tt < 8; tt++) acc[tt] = 0.f;
    int h = tid;
    #pragma unroll 4
    for (int s = 0; s < Tv; s++) {
        float hv = d_Hsh[((b * Tv) + s) * Hv + h];
        #pragma unroll
        for (int tt = 0; tt < 8; tt++) acc[tt] = fmaf(sb[tt][s], hv, acc[tt]);
    }
    #pragma unroll
    for (int tt = 0; tt < 8; tt++)
        d_R[((b * Tv) + (t0 + tt)) * Hv + h] = acc[tt];
}

// ---------------- launch ----------------
extern "C" void kernel_launch(void* const* d_in, const int* in_sizes, int n_in,
                              void* d_out, int out_size) {
    const float* x       = (const float*)d_in[0];
    const float* Wih_s   = (const float*)d_in[1];
    const float* Whh_s   = (const float*)d_in[2];
    const float* b_lstms = (const float*)d_in[3];
    const float* Wx      = (const float*)d_in[4];
    const float* Wht     = (const float*)d_in[5];
    const float* Whs     = (const float*)d_in[6];
    const float* bs      = (const float*)d_in[7];
    const float* u       = (const float*)d_in[8];
    const float* bu      = (const float*)d_in[9];
    const float* Wih_t   = (const float*)d_in[10];
    const float* Whh_t   = (const float*)d_in[11];
    const float* b_lstmt = (const float*)d_in[12];
    float* out = (float*)d_out;

    dim3 tb(32, 8);
    k_transpose<<<dim3(4, 16), tb>>>(Wih_s, 0, Gv, Iv);
    k_transpose<<<dim3(8, 16), tb>>>(Wih_t, 1, Gv, Iv + Hv);
    k_packw<<<32, 256>>>(Whh_s, 0);
    k_packw<<<32, 256>>>(Whh_t, 1);

    // shared LSTM
    k_proj_gates<<<dim3(Tv / 4, Bv), 512>>>(x, b_lstms, 0);
    k_lstm<<<1, 512>>>(0, out);

    // attention
    k_att_proj<<<dim3(Tv / 8, Bv), 128>>>(x, Wx, Wht, Whs, bs);
    k_scores<<<dim3(Tv / 32, Tv / 32, Bv), dim3(32, 8)>>>(u, bu);
    k_softmax<<<Bv * Tv, 256>>>();
    k_R<<<dim3(Tv / 8, Bv), 128>>>();

    // task LSTM
    k_proj_gates<<<dim3(Tv / 4, Bv), 512>>>(x, b_lstmt, 1);
    k_lstm<<<1, 512>>>(1, out);
}